// round 3
// baseline (speedup 1.0000x reference)
#include <cuda_runtime.h>

// Problem constants
#define TT    256
#define BATCH 4096
#define H1    16
#define H2    64
#define BB    28          // batch tile per layer-2 block
#define L2_THREADS 192    // one thread per gate row (3*H2)

// ---------------------------------------------------------------------------
// Scratch (static device globals — no allocation allowed)
// ---------------------------------------------------------------------------
__device__ float g_out1[(size_t)TT * BATCH * H1];   // layer-1 outputs [T][B][16]  (64 MB)
__device__ float g_h[2 * (size_t)BATCH * H2];       // final hidden per dir [2][B][64]

// ---------------------------------------------------------------------------
// Fast activations (fp32, MUFU-based)
// ---------------------------------------------------------------------------
__device__ __forceinline__ float sigf(float x) {
    return __fdividef(1.0f, 1.0f + __expf(-x));
}
__device__ __forceinline__ float tanhfast(float x) {
    return fmaf(2.0f, __fdividef(1.0f, 1.0f + __expf(-2.0f * x)), -1.0f);
}
__device__ __forceinline__ float gru_comb(float gr, float gz, float gn, float gx, float h) {
    float r = sigf(gr);
    float z = sigf(gz);
    float n = tanhfast(fmaf(r, gn, gx));
    return fmaf(z, h - n, n);   // (1-z)*n + z*h
}

// ---------------------------------------------------------------------------
// Layer 1: GRU(2 -> 16).  Block = 256 threads = 16 batch x 16 hidden units.
// Writes out1[t][b][j] for all t.
// ---------------------------------------------------------------------------
__global__ void gru1_kernel(const float* __restrict__ traj,
                            const float* __restrict__ w_ih1,
                            const float* __restrict__ w_hh1,
                            const float* __restrict__ b_ih1,
                            const float* __restrict__ b_hh1) {
    __shared__ float4 s_w4[16 * 16];   // [k][j] -> (w_r, w_z, w_n, 0)
    __shared__ float  s_h[16 * 17];    // [b_local][k], padded

    const int tid = threadIdx.x;
    const int bl  = tid >> 4;   // 0..15 batch-local
    const int j   = tid & 15;   // hidden unit
    const int gb  = blockIdx.x * 16 + bl;

    // pack recurrent weights transposed: s_w4[k][j]
    {
        int k = tid >> 4, jj = tid & 15;
        s_w4[k * 16 + jj] = make_float4(w_hh1[(jj)      * 16 + k],
                                        w_hh1[(16 + jj) * 16 + k],
                                        w_hh1[(32 + jj) * 16 + k],
                                        0.0f);
    }
    s_h[bl * 17 + j] = 0.0f;

    // per-thread constants
    const float wxr0 = w_ih1[j * 2 + 0],        wxr1 = w_ih1[j * 2 + 1];
    const float wxz0 = w_ih1[(16 + j) * 2 + 0], wxz1 = w_ih1[(16 + j) * 2 + 1];
    const float wxn0 = w_ih1[(32 + j) * 2 + 0], wxn1 = w_ih1[(32 + j) * 2 + 1];
    const float br  = b_ih1[j]      + b_hh1[j];
    const float bz  = b_ih1[16 + j] + b_hh1[16 + j];
    const float bxn = b_ih1[32 + j];
    const float bhn = b_hh1[32 + j];
    __syncthreads();

    const float2* xp = (const float2*)(traj + (size_t)gb * TT * 2);
    float* op = g_out1 + (size_t)gb * 16 + j;

    float2 xv = xp[0];   // prefetch t=0
    for (int t = 0; t < TT; ++t) {
        float x0 = xv.x, x1 = xv.y;
        if (t + 1 < TT) xv = xp[t + 1];          // overlap LDG with compute

        float ar  = fmaf(wxr1, x1, fmaf(wxr0, x0, br));
        float az  = fmaf(wxz1, x1, fmaf(wxz0, x0, bz));
        float axn = fmaf(wxn1, x1, fmaf(wxn0, x0, bxn));
        float ahn = bhn;
        float hold = s_h[bl * 17 + j];
#pragma unroll
        for (int k = 0; k < 16; ++k) {
            float  h = s_h[bl * 17 + k];
            float4 w = s_w4[k * 16 + j];
            ar  = fmaf(w.x, h, ar);
            az  = fmaf(w.y, h, az);
            ahn = fmaf(w.z, h, ahn);
        }
        float r = sigf(ar);
        float z = sigf(az);
        float n = tanhfast(fmaf(r, ahn, axn));
        float hnew = fmaf(z, hold - n, n);
        __syncthreads();
        s_h[bl * 17 + j] = hnew;
        op[(size_t)t * BATCH * 16] = hnew;
        __syncthreads();
    }
}

// ---------------------------------------------------------------------------
// Layer 2: bidirectional GRU(16 -> 64), last hidden only.
// grid = (147, 2): blockIdx.y = direction.  192 threads, BB=28 batch per block.
// Thread j owns gate-row j; weights for row j live in REGISTERS (80 floats),
// so dynamic smem stays below the 48 KB no-opt-in limit.
// Dynamic smem layout (floats):
//   s_bih[192] s_bhh[192] s_g[192*28] s_gxn[64*28] s_hT[64*28] s_xT[16*28]
// ---------------------------------------------------------------------------
#define SM2_BIH 0
#define SM2_BHH 192
#define SM2_G   384
#define SM2_GXN 5760
#define SM2_HT  7552
#define SM2_XT  9344
#define SM2_TOTAL 9792   // floats -> 39168 bytes (< 48 KB, no attribute needed)

__global__ void __launch_bounds__(L2_THREADS, 2)
gru2_kernel(const float* __restrict__ w_ihf, const float* __restrict__ w_hhf,
            const float* __restrict__ b_ihf, const float* __restrict__ b_hhf,
            const float* __restrict__ w_ihb, const float* __restrict__ w_hhb,
            const float* __restrict__ b_ihb, const float* __restrict__ b_hhb) {
    extern __shared__ float sm[];
    float* s_bih = sm + SM2_BIH;
    float* s_bhh = sm + SM2_BHH;
    float* s_g   = sm + SM2_G;
    float* s_gxn = sm + SM2_GXN;
    float* s_hT  = sm + SM2_HT;
    float* s_xT  = sm + SM2_XT;

    const int dir = blockIdx.y;
    const float* w_ih = dir ? w_ihb : w_ihf;
    const float* w_hh = dir ? w_hhb : w_hhf;
    const float* b_ih = dir ? b_ihb : b_ihf;
    const float* b_hh = dir ? b_hhb : b_hhf;

    const int j  = threadIdx.x;          // 0..191, owns gate row j
    const int b0 = blockIdx.x * BB;

    // Row-j weights into registers. Rows are contiguous and 16B-aligned.
    float wih_r[16];
    float whh_r[64];
    {
        const float4* p = (const float4*)(w_ih + j * 16);
#pragma unroll
        for (int i = 0; i < 4; ++i) {
            float4 v = p[i];
            wih_r[i * 4 + 0] = v.x; wih_r[i * 4 + 1] = v.y;
            wih_r[i * 4 + 2] = v.z; wih_r[i * 4 + 3] = v.w;
        }
        const float4* q = (const float4*)(w_hh + j * 64);
#pragma unroll
        for (int i = 0; i < 16; ++i) {
            float4 v = q[i];
            whh_r[i * 4 + 0] = v.x; whh_r[i * 4 + 1] = v.y;
            whh_r[i * 4 + 2] = v.z; whh_r[i * 4 + 3] = v.w;
        }
    }
    s_bih[j] = b_ih[j];
    s_bhh[j] = b_hh[j];
    for (int idx = j; idx < H2 * BB; idx += L2_THREADS) s_hT[idx] = 0.0f;
    __syncthreads();

    const float binit_rz = s_bih[j] + s_bhh[j];
    const float binit_n  = s_bih[j];
    const float bhh_j    = s_bhh[j];
    const float binit    = (j < 128) ? binit_rz : binit_n;

    for (int step = 0; step < TT; ++step) {
        const int t = dir ? (TT - 1 - step) : step;

        // stage x tile (transposed): s_xT[k][b]
        for (int idx = j; idx < 16 * BB; idx += L2_THREADS) {
            int bl = idx >> 4, k = idx & 15;
            int gb = b0 + bl; if (gb >= BATCH) gb = BATCH - 1;
            s_xT[k * BB + bl] = g_out1[(size_t)t * BATCH * 16 + (size_t)gb * 16 + k];
        }
        __syncthreads();

        float4 acc[7];
#pragma unroll
        for (int i = 0; i < 7; ++i) acc[i] = make_float4(binit, binit, binit, binit);

        // input projection: k = 0..15 (weights in registers, x via broadcast LDS.128)
#pragma unroll
        for (int k = 0; k < 16; ++k) {
            float w = wih_r[k];
            const float4* xv = (const float4*)(s_xT + k * BB);
#pragma unroll
            for (int i = 0; i < 7; ++i) {
                float4 x = xv[i];
                acc[i].x = fmaf(w, x.x, acc[i].x);
                acc[i].y = fmaf(w, x.y, acc[i].y);
                acc[i].z = fmaf(w, x.z, acc[i].z);
                acc[i].w = fmaf(w, x.w, acc[i].w);
            }
        }
        // n-gate keeps x-proj separate (needed inside tanh with r*hn)
        if (j >= 128) {
            float4* d = (float4*)(s_gxn + (j - 128) * BB);
#pragma unroll
            for (int i = 0; i < 7; ++i) {
                d[i] = acc[i];
                acc[i] = make_float4(bhh_j, bhh_j, bhh_j, bhh_j);
            }
        }
        // recurrent projection: k = 0..63 (fully unrolled so whh_r stays in RF)
#pragma unroll
        for (int k = 0; k < 64; ++k) {
            float w = whh_r[k];
            const float4* hv = (const float4*)(s_hT + k * BB);
#pragma unroll
            for (int i = 0; i < 7; ++i) {
                float4 h = hv[i];
                acc[i].x = fmaf(w, h.x, acc[i].x);
                acc[i].y = fmaf(w, h.y, acc[i].y);
                acc[i].z = fmaf(w, h.z, acc[i].z);
                acc[i].w = fmaf(w, h.w, acc[i].w);
            }
        }
        {
            float4* d = (float4*)(s_g + j * BB);
#pragma unroll
            for (int i = 0; i < 7; ++i) d[i] = acc[i];
        }
        __syncthreads();

        // epilogue: 448 float4 work items (64 hidden x 7 chunks) over 192 threads
        for (int item = j; item < 64 * 7; item += L2_THREADS) {
            int jj = item & 63;
            int i  = item >> 6;
            float4 vr = *(const float4*)(s_g   + jj        * BB + i * 4);
            float4 vz = *(const float4*)(s_g   + (64 + jj) * BB + i * 4);
            float4 vn = *(const float4*)(s_g   + (128 + jj)* BB + i * 4);
            float4 vx = *(const float4*)(s_gxn + jj        * BB + i * 4);
            float4* hp = (float4*)(s_hT + jj * BB + i * 4);
            float4 vh = *hp;
            float4 o;
            o.x = gru_comb(vr.x, vz.x, vn.x, vx.x, vh.x);
            o.y = gru_comb(vr.y, vz.y, vn.y, vx.y, vh.y);
            o.z = gru_comb(vr.z, vz.z, vn.z, vx.z, vh.z);
            o.w = gru_comb(vr.w, vz.w, vn.w, vx.w, vh.w);
            *hp = o;
        }
        __syncthreads();
    }

    // write final hidden state (coalesced over hidden index)
    for (int idx = j; idx < H2 * BB; idx += L2_THREADS) {
        int bl = idx >> 6, k = idx & 63;
        int gb = b0 + bl;
        if (gb < BATCH)
            g_h[(size_t)dir * BATCH * H2 + (size_t)gb * H2 + k] = s_hT[k * BB + bl];
    }
}

// ---------------------------------------------------------------------------
// MLP: out = ((h_fwd + h_bwd) @ W1^T + b1) @ W2^T + b2   (no activation)
// Block = 256 threads = 8 batch x 32 (warp == one batch element).
// ---------------------------------------------------------------------------
__global__ void mlp_kernel(const float* __restrict__ W1, const float* __restrict__ b1,
                           const float* __restrict__ W2, const float* __restrict__ b2,
                           float* __restrict__ out) {
    __shared__ float s_w1t[64 * 32];  // [k][m]
    __shared__ float s_w2t[32 * 8];   // [k][o]
    __shared__ float s_b1[32];
    __shared__ float s_b2[8];
    __shared__ float s_m1[8 * 32];

    const int tid = threadIdx.x;
    for (int idx = tid; idx < 32 * 64; idx += 256) {
        int m = idx >> 6, k = idx & 63;
        s_w1t[k * 32 + m] = W1[idx];
    }
    if (tid < 8 * 32) { int o = tid >> 5, k = tid & 31; s_w2t[k * 8 + o] = W2[tid]; }
    if (tid < 32) s_b1[tid] = b1[tid];
    if (tid < 8)  s_b2[tid] = b2[tid];
    __syncthreads();

    const int bl = tid >> 5;        // warp index == batch-local
    const int m  = tid & 31;
    const int gb = blockIdx.x * 8 + bl;

    const float* hf = g_h + (size_t)gb * H2;
    const float* hb = g_h + (size_t)(BATCH + gb) * H2;

    float acc = s_b1[m];
#pragma unroll
    for (int k = 0; k < 64; ++k)
        acc = fmaf(s_w1t[k * 32 + m], hf[k] + hb[k], acc);
    s_m1[bl * 32 + m] = acc;
    __syncthreads();

    if (m < 8) {
        float a2 = s_b2[m];
#pragma unroll
        for (int k = 0; k < 32; ++k)
            a2 = fmaf(s_w2t[k * 8 + m], s_m1[bl * 32 + k], a2);
        out[(size_t)gb * 8 + m] = a2;
    }
}

// ---------------------------------------------------------------------------
// Launch (no attribute calls, no allocation, graph-capturable)
// ---------------------------------------------------------------------------
extern "C" void kernel_launch(void* const* d_in, const int* in_sizes, int n_in,
                              void* d_out, int out_size) {
    const float* traj   = (const float*)d_in[0];
    const float* w_ih1  = (const float*)d_in[1];
    const float* w_hh1  = (const float*)d_in[2];
    const float* b_ih1  = (const float*)d_in[3];
    const float* b_hh1  = (const float*)d_in[4];
    const float* w_ih2f = (const float*)d_in[5];
    const float* w_hh2f = (const float*)d_in[6];
    const float* b_ih2f = (const float*)d_in[7];
    const float* b_hh2f = (const float*)d_in[8];
    const float* w_ih2b = (const float*)d_in[9];
    const float* w_hh2b = (const float*)d_in[10];
    const float* b_ih2b = (const float*)d_in[11];
    const float* b_hh2b = (const float*)d_in[12];
    const float* W1     = (const float*)d_in[13];
    const float* b1     = (const float*)d_in[14];
    const float* W2     = (const float*)d_in[15];
    const float* b2     = (const float*)d_in[16];

    gru1_kernel<<<BATCH / 16, 256>>>(traj, w_ih1, w_hh1, b_ih1, b_hh1);

    dim3 grid2((BATCH + BB - 1) / BB, 2);               // (147, 2)
    gru2_kernel<<<grid2, L2_THREADS, SM2_TOTAL * sizeof(float)>>>(
        w_ih2f, w_hh2f, b_ih2f, b_hh2f,
        w_ih2b, w_hh2b, b_ih2b, b_hh2b);

    mlp_kernel<<<BATCH / 8, 256>>>(W1, b1, W2, b2, (float*)d_out);
}

// round 4
// speedup vs baseline: 1.1221x; 1.1221x over previous
#include <cuda_runtime.h>

// Problem constants
#define TT    256
#define BATCH 4096
#define H1    16
#define H2    64
#define BB    28          // batch tile per layer-2 block (14 packed f32x2 lanes)
#define L2_THREADS 192    // one thread per gate row (3*H2)

typedef unsigned long long u64;

// ---------------------------------------------------------------------------
// Scratch (static device globals — no allocation allowed)
// ---------------------------------------------------------------------------
__device__ float g_out1[(size_t)TT * BATCH * H1];   // layer-1 outputs [T][B][16]
__device__ float g_h[2 * (size_t)BATCH * H2];       // final hidden per dir [2][B][64]

// ---------------------------------------------------------------------------
// Packed f32x2 helpers (Blackwell, PTX ISA 8.6+, sm_100+)
// ---------------------------------------------------------------------------
#define FMA2(d, a, b, c) \
    asm("fma.rn.f32x2 %0, %1, %2, %3;" : "=l"(d) : "l"(a), "l"(b), "l"(c))
__device__ __forceinline__ u64 pack2(float x) {
    u64 d;
    asm("mov.b64 %0, {%1, %1};" : "=l"(d) : "f"(x));
    return d;
}

// ---------------------------------------------------------------------------
// Fast activations (fp32, MUFU-based)
// ---------------------------------------------------------------------------
__device__ __forceinline__ float sigf(float x) {
    return __fdividef(1.0f, 1.0f + __expf(-x));
}
__device__ __forceinline__ float tanhfast(float x) {
    return fmaf(2.0f, __fdividef(1.0f, 1.0f + __expf(-2.0f * x)), -1.0f);
}
__device__ __forceinline__ float gru_comb(float gr, float gz, float gn, float gx, float h) {
    float r = sigf(gr);
    float z = sigf(gz);
    float n = tanhfast(fmaf(r, gn, gx));
    return fmaf(z, h - n, n);   // (1-z)*n + z*h
}

// ---------------------------------------------------------------------------
// Layer 1: GRU(2 -> 16).  512 threads = 32 batch x 16 hidden; 128 blocks
// (one clean wave on 148 SMs).  Double-buffered h -> ONE barrier per step.
// ---------------------------------------------------------------------------
__global__ void __launch_bounds__(512)
gru1_kernel(const float* __restrict__ traj,
            const float* __restrict__ w_ih1,
            const float* __restrict__ w_hh1,
            const float* __restrict__ b_ih1,
            const float* __restrict__ b_hh1) {
    __shared__ float4 s_w4[16 * 16];    // [k][j] -> (w_r, w_z, w_n, 0)
    __shared__ float  s_h[2][32 * 17];  // double buffer, padded

    const int tid = threadIdx.x;
    const int bl  = tid >> 4;   // 0..31 batch-local
    const int j   = tid & 15;   // hidden unit
    const int gb  = blockIdx.x * 32 + bl;

    if (tid < 256) {
        int k = tid >> 4, jj = tid & 15;
        s_w4[k * 16 + jj] = make_float4(w_hh1[(jj)      * 16 + k],
                                        w_hh1[(16 + jj) * 16 + k],
                                        w_hh1[(32 + jj) * 16 + k],
                                        0.0f);
    }
    s_h[0][bl * 17 + j] = 0.0f;

    const float wxr0 = w_ih1[j * 2 + 0],        wxr1 = w_ih1[j * 2 + 1];
    const float wxz0 = w_ih1[(16 + j) * 2 + 0], wxz1 = w_ih1[(16 + j) * 2 + 1];
    const float wxn0 = w_ih1[(32 + j) * 2 + 0], wxn1 = w_ih1[(32 + j) * 2 + 1];
    const float br  = b_ih1[j]      + b_hh1[j];
    const float bz  = b_ih1[16 + j] + b_hh1[16 + j];
    const float bxn = b_ih1[32 + j];
    const float bhn = b_hh1[32 + j];
    __syncthreads();

    const float2* xp = (const float2*)(traj + (size_t)gb * TT * 2);
    float* op = g_out1 + (size_t)gb * 16 + j;

    float2 xv = xp[0];   // prefetch t=0
    int p = 0;
    for (int t = 0; t < TT; ++t) {
        float x0 = xv.x, x1 = xv.y;
        if (t + 1 < TT) xv = xp[t + 1];          // overlap LDG with compute

        float ar  = fmaf(wxr1, x1, fmaf(wxr0, x0, br));
        float az  = fmaf(wxz1, x1, fmaf(wxz0, x0, bz));
        float axn = fmaf(wxn1, x1, fmaf(wxn0, x0, bxn));
        float ahn = bhn;
        float hold = s_h[p][bl * 17 + j];
#pragma unroll
        for (int k = 0; k < 16; ++k) {
            float  h = s_h[p][bl * 17 + k];
            float4 w = s_w4[k * 16 + j];
            ar  = fmaf(w.x, h, ar);
            az  = fmaf(w.y, h, az);
            ahn = fmaf(w.z, h, ahn);
        }
        float r = sigf(ar);
        float z = sigf(az);
        float n = tanhfast(fmaf(r, ahn, axn));
        float hnew = fmaf(z, hold - n, n);
        s_h[1 - p][bl * 17 + j] = hnew;      // write OTHER buffer: no pre-sync needed
        op[(size_t)t * BATCH * 16] = hnew;
        p ^= 1;
        __syncthreads();                     // single barrier per step
    }
}

// ---------------------------------------------------------------------------
// Layer 2: bidirectional GRU(16 -> 64), last hidden only.
// grid = (147, 2).  192 threads; thread j owns gate-row j (weights in regs).
// Accumulators are packed f32x2 (fma.rn.f32x2) -> half the FFMA issue count.
// 2 barriers/step; next-step x tile prefetched into regs behind the mainloop.
// Dynamic smem (floats):
//   s_bih[192] s_bhh[192] s_g[192*28] s_gxn[64*28] s_hT[64*28] s_xT[16*28]
// ---------------------------------------------------------------------------
#define SM2_BIH 0
#define SM2_BHH 192
#define SM2_G   384
#define SM2_GXN 5760
#define SM2_HT  7552
#define SM2_XT  9344
#define SM2_TOTAL 9792   // 39168 bytes (< 48 KB, no attribute call needed)

__global__ void __launch_bounds__(L2_THREADS, 2)
gru2_kernel(const float* __restrict__ w_ihf, const float* __restrict__ w_hhf,
            const float* __restrict__ b_ihf, const float* __restrict__ b_hhf,
            const float* __restrict__ w_ihb, const float* __restrict__ w_hhb,
            const float* __restrict__ b_ihb, const float* __restrict__ b_hhb) {
    extern __shared__ float sm[];
    float* s_bih = sm + SM2_BIH;
    float* s_bhh = sm + SM2_BHH;
    float* s_g   = sm + SM2_G;
    float* s_gxn = sm + SM2_GXN;
    float* s_hT  = sm + SM2_HT;
    float* s_xT  = sm + SM2_XT;

    const int dir = blockIdx.y;
    const float* w_ih = dir ? w_ihb : w_ihf;
    const float* w_hh = dir ? w_hhb : w_hhf;
    const float* b_ih = dir ? b_ihb : b_ihf;
    const float* b_hh = dir ? b_hhb : b_hhf;

    const int j  = threadIdx.x;          // 0..191, owns gate row j
    const int b0 = blockIdx.x * BB;

    // Row-j weights into registers (rows contiguous, 16B-aligned).
    float wih_r[16];
    float whh_r[64];
    {
        const float4* pw = (const float4*)(w_ih + j * 16);
#pragma unroll
        for (int i = 0; i < 4; ++i) {
            float4 v = pw[i];
            wih_r[i * 4 + 0] = v.x; wih_r[i * 4 + 1] = v.y;
            wih_r[i * 4 + 2] = v.z; wih_r[i * 4 + 3] = v.w;
        }
        const float4* qw = (const float4*)(w_hh + j * 64);
#pragma unroll
        for (int i = 0; i < 16; ++i) {
            float4 v = qw[i];
            whh_r[i * 4 + 0] = v.x; whh_r[i * 4 + 1] = v.y;
            whh_r[i * 4 + 2] = v.z; whh_r[i * 4 + 3] = v.w;
        }
    }
    s_bih[j] = b_ih[j];
    s_bhh[j] = b_hh[j];
    for (int idx = j; idx < H2 * BB; idx += L2_THREADS) s_hT[idx] = 0.0f;
    __syncthreads();

    const float binit = (j < 128) ? (s_bih[j] + s_bhh[j]) : s_bih[j];
    const u64 binit2  = pack2(binit);
    const u64 bhh2    = pack2(s_bhh[j]);

    // ---- x-tile prefetch bookkeeping: 448 items over 192 threads (<=3 each)
    int    pf_sm[3];
    size_t pf_gm[3];
    int    pf_n = 0;
#pragma unroll
    for (int c = 0; c < 3; ++c) {
        int idx = j + c * L2_THREADS;
        if (idx < 16 * BB) {
            int bl = idx >> 4, k = idx & 15;
            int gb = b0 + bl; if (gb >= BATCH) gb = BATCH - 1;
            pf_sm[c] = k * BB + bl;
            pf_gm[c] = (size_t)gb * 16 + k;
            pf_n = c + 1;
        }
    }
    float pf[3];
    {
        const int t0 = dir ? (TT - 1) : 0;
#pragma unroll
        for (int c = 0; c < 3; ++c)
            if (c < pf_n) pf[c] = g_out1[(size_t)t0 * BATCH * 16 + pf_gm[c]];
    }

    for (int step = 0; step < TT; ++step) {
        // commit prefetched x tile for this step
#pragma unroll
        for (int c = 0; c < 3; ++c)
            if (c < pf_n) s_xT[pf_sm[c]] = pf[c];
        __syncthreads();   // x visible; also orders prev-step s_hT writes

        // kick off next step's x loads (hidden behind the mainloop)
        {
            int ns = step + 1 < TT ? step + 1 : step;
            int tn = dir ? (TT - 1 - ns) : ns;
#pragma unroll
            for (int c = 0; c < 3; ++c)
                if (c < pf_n) pf[c] = g_out1[(size_t)tn * BATCH * 16 + pf_gm[c]];
        }

        u64 acc[14];
#pragma unroll
        for (int i = 0; i < 14; ++i) acc[i] = binit2;

        // input projection: k = 0..15
#pragma unroll
        for (int k = 0; k < 16; ++k) {
            u64 w2 = pack2(wih_r[k]);
            const ulonglong2* xv = (const ulonglong2*)(s_xT + k * BB);
#pragma unroll
            for (int i = 0; i < 7; ++i) {
                ulonglong2 x = xv[i];   // LDS.128 broadcast
                FMA2(acc[2 * i],     w2, x.x, acc[2 * i]);
                FMA2(acc[2 * i + 1], w2, x.y, acc[2 * i + 1]);
            }
        }
        // n-gate keeps x-proj separate (needed inside tanh with r*hn)
        if (j >= 128) {
            ulonglong2* d = (ulonglong2*)(s_gxn + (j - 128) * BB);
#pragma unroll
            for (int i = 0; i < 7; ++i) {
                d[i] = make_ulonglong2(acc[2 * i], acc[2 * i + 1]);
                acc[2 * i] = bhh2; acc[2 * i + 1] = bhh2;
            }
        }
        // recurrent projection: k = 0..63
#pragma unroll
        for (int k = 0; k < 64; ++k) {
            u64 w2 = pack2(whh_r[k]);
            const ulonglong2* hv = (const ulonglong2*)(s_hT + k * BB);
#pragma unroll
            for (int i = 0; i < 7; ++i) {
                ulonglong2 h = hv[i];
                FMA2(acc[2 * i],     w2, h.x, acc[2 * i]);
                FMA2(acc[2 * i + 1], w2, h.y, acc[2 * i + 1]);
            }
        }
        {
            ulonglong2* d = (ulonglong2*)(s_g + j * BB);
#pragma unroll
            for (int i = 0; i < 7; ++i)
                d[i] = make_ulonglong2(acc[2 * i], acc[2 * i + 1]);
        }
        __syncthreads();

        // epilogue: 448 float4 items (64 hidden x 7 chunks) over 192 threads
        for (int item = j; item < 64 * 7; item += L2_THREADS) {
            int jj = item & 63;
            int i  = item >> 6;
            float4 vr = *(const float4*)(s_g   + jj         * BB + i * 4);
            float4 vz = *(const float4*)(s_g   + (64 + jj)  * BB + i * 4);
            float4 vn = *(const float4*)(s_g   + (128 + jj) * BB + i * 4);
            float4 vx = *(const float4*)(s_gxn + jj         * BB + i * 4);
            float4* hp = (float4*)(s_hT + jj * BB + i * 4);
            float4 vh = *hp;
            float4 o;
            o.x = gru_comb(vr.x, vz.x, vn.x, vx.x, vh.x);
            o.y = gru_comb(vr.y, vz.y, vn.y, vx.y, vh.y);
            o.z = gru_comb(vr.z, vz.z, vn.z, vx.z, vh.z);
            o.w = gru_comb(vr.w, vz.w, vn.w, vx.w, vh.w);
            *hp = o;
        }
        // no barrier here: next iteration's post-commit barrier orders s_hT
    }
    __syncthreads();

    // write final hidden state (coalesced over hidden index)
    for (int idx = j; idx < H2 * BB; idx += L2_THREADS) {
        int bl = idx >> 6, k = idx & 63;
        int gb = b0 + bl;
        if (gb < BATCH)
            g_h[(size_t)dir * BATCH * H2 + (size_t)gb * H2 + k] = s_hT[k * BB + bl];
    }
}

// ---------------------------------------------------------------------------
// MLP: out = ((h_fwd + h_bwd) @ W1^T + b1) @ W2^T + b2
// ---------------------------------------------------------------------------
__global__ void mlp_kernel(const float* __restrict__ W1, const float* __restrict__ b1,
                           const float* __restrict__ W2, const float* __restrict__ b2,
                           float* __restrict__ out) {
    __shared__ float s_w1t[64 * 32];
    __shared__ float s_w2t[32 * 8];
    __shared__ float s_b1[32];
    __shared__ float s_b2[8];
    __shared__ float s_m1[8 * 32];

    const int tid = threadIdx.x;
    for (int idx = tid; idx < 32 * 64; idx += 256) {
        int m = idx >> 6, k = idx & 63;
        s_w1t[k * 32 + m] = W1[idx];
    }
    if (tid < 8 * 32) { int o = tid >> 5, k = tid & 31; s_w2t[k * 8 + o] = W2[tid]; }
    if (tid < 32) s_b1[tid] = b1[tid];
    if (tid < 8)  s_b2[tid] = b2[tid];
    __syncthreads();

    const int bl = tid >> 5;
    const int m  = tid & 31;
    const int gb = blockIdx.x * 8 + bl;

    const float* hf = g_h + (size_t)gb * H2;
    const float* hb = g_h + (size_t)(BATCH + gb) * H2;

    float acc = s_b1[m];
#pragma unroll
    for (int k = 0; k < 64; ++k)
        acc = fmaf(s_w1t[k * 32 + m], hf[k] + hb[k], acc);
    s_m1[bl * 32 + m] = acc;
    __syncthreads();

    if (m < 8) {
        float a2 = s_b2[m];
#pragma unroll
        for (int k = 0; k < 32; ++k)
            a2 = fmaf(s_w2t[k * 8 + m], s_m1[bl * 32 + k], a2);
        out[(size_t)gb * 8 + m] = a2;
    }
}

// ---------------------------------------------------------------------------
// Launch (no attribute calls, no allocation, graph-capturable)
// ---------------------------------------------------------------------------
extern "C" void kernel_launch(void* const* d_in, const int* in_sizes, int n_in,
                              void* d_out, int out_size) {
    const float* traj   = (const float*)d_in[0];
    const float* w_ih1  = (const float*)d_in[1];
    const float* w_hh1  = (const float*)d_in[2];
    const float* b_ih1  = (const float*)d_in[3];
    const float* b_hh1  = (const float*)d_in[4];
    const float* w_ih2f = (const float*)d_in[5];
    const float* w_hh2f = (const float*)d_in[6];
    const float* b_ih2f = (const float*)d_in[7];
    const float* b_hh2f = (const float*)d_in[8];
    const float* w_ih2b = (const float*)d_in[9];
    const float* w_hh2b = (const float*)d_in[10];
    const float* b_ih2b = (const float*)d_in[11];
    const float* b_hh2b = (const float*)d_in[12];
    const float* W1     = (const float*)d_in[13];
    const float* b1     = (const float*)d_in[14];
    const float* W2     = (const float*)d_in[15];
    const float* b2     = (const float*)d_in[16];

    gru1_kernel<<<BATCH / 32, 512>>>(traj, w_ih1, w_hh1, b_ih1, b_hh1);

    dim3 grid2((BATCH + BB - 1) / BB, 2);               // (147, 2)
    gru2_kernel<<<grid2, L2_THREADS, SM2_TOTAL * sizeof(float)>>>(
        w_ih2f, w_hh2f, b_ih2f, b_hh2f,
        w_ih2b, w_hh2b, b_ih2b, b_hh2b);

    mlp_kernel<<<BATCH / 8, 256>>>(W1, b1, W2, b2, (float*)d_out);
}